// round 8
// baseline (speedup 1.0000x reference)
#include <cuda_runtime.h>
#include <math.h>
#include <stdint.h>

#define NB   2
#define SEQ  2048
#define EMB  1024
#define NH   16
#define NKV  8
#define HD   64
#define MROWS (NB*SEQ)   // 4096

// ---------------- scratch (no allocations allowed) ----------------
__device__ float g_q[(size_t)MROWS * NH * HD];    // 16 MB (QSC-scaled, tf32-rounded)
__device__ float g_k[(size_t)MROWS * NKV * HD];   // 8 MB  (tf32-rounded)
__device__ float g_v[(size_t)MROWS * NKV * HD];   // 8 MB  (tf32-rounded)
__device__ float g_attn[(size_t)MROWS * NH * HD]; // 16 MB

#define QSC 0.18033688011112042f   // 0.125 * log2(e)

// =====================================================================
// helpers
// =====================================================================
__device__ __forceinline__ uint32_t f2tf(float f) {
    uint32_t u;
    asm("cvt.rna.tf32.f32 %0, %1;" : "=r"(u) : "f"(f));
    return u;
}
__device__ __forceinline__ void mma_tf32(float* d, const uint32_t* a, const uint32_t* b) {
    asm volatile(
        "mma.sync.aligned.m16n8k8.row.col.f32.tf32.tf32.f32 "
        "{%0,%1,%2,%3}, {%4,%5,%6,%7}, {%8,%9}, {%0,%1,%2,%3};"
        : "+f"(d[0]), "+f"(d[1]), "+f"(d[2]), "+f"(d[3])
        : "r"(a[0]), "r"(a[1]), "r"(a[2]), "r"(a[3]), "r"(b[0]), "r"(b[1]));
}
__device__ __forceinline__ uint32_t smem_u32(const void* p) {
    uint32_t a;
    asm("{ .reg .u64 t; cvta.to.shared.u64 t, %1; cvt.u32.u64 %0, t; }" : "=r"(a) : "l"(p));
    return a;
}
#define CP16(dst, src) \
    asm volatile("cp.async.cg.shared.global [%0], [%1], 16;" :: "r"(dst), "l"(src))
#define CP_COMMIT() asm volatile("cp.async.commit_group;" ::: "memory")
#define CP_WAIT(n)  asm volatile("cp.async.wait_group %0;" :: "n"(n) : "memory")

// =====================================================================
// mma.sync tf32 GEMM body: C[M,N] = A[M,K] @ B[N,K]^T
// mode 0: +bias (plain fp32 out); mode 1: tf32-rounded out;
// mode 2: QSC-scaled + tf32-rounded out.
// =====================================================================
#define LT 36

__device__ __forceinline__
void gemm_body(const float* __restrict__ A, const float* __restrict__ B,
               const float* __restrict__ bias, float* __restrict__ C,
               int N, int K, int m0, int n0, int mode)
{
    __shared__ uint32_t As[128][LT];
    __shared__ uint32_t Bs[128][LT];

    const int tid  = threadIdx.x;
    const int lane = tid & 31;
    const int wid  = tid >> 5;
    const int wm   = wid >> 2;
    const int wn   = wid & 3;

    const int srow = tid >> 3;
    const int sc4  = (tid & 7) * 4;

    float acc[4][4][4];
#pragma unroll
    for (int mt = 0; mt < 4; mt++)
#pragma unroll
        for (int nt = 0; nt < 4; nt++)
#pragma unroll
            for (int i = 0; i < 4; i++) acc[mt][nt][i] = 0.f;

    float4 ra[4], rb[4];

#pragma unroll
    for (int p = 0; p < 4; p++) {
        int row = srow + p * 32;
        ra[p] = *(const float4*)(A + (size_t)(m0 + row) * K + sc4);
        rb[p] = *(const float4*)(B + (size_t)(n0 + row) * K + sc4);
    }
#pragma unroll
    for (int p = 0; p < 4; p++) {
        int row = srow + p * 32;
        uint4 ta = { f2tf(ra[p].x), f2tf(ra[p].y), f2tf(ra[p].z), f2tf(ra[p].w) };
        *(uint4*)&As[row][sc4] = ta;
        uint4 tb = { f2tf(rb[p].x), f2tf(rb[p].y), f2tf(rb[p].z), f2tf(rb[p].w) };
        *(uint4*)&Bs[row][sc4] = tb;
    }
    __syncthreads();

    const int NC = K / 32;
    const int fr = lane >> 2;
    const int fc = lane & 3;

    for (int ch = 0; ch < NC; ch++) {
        if (ch + 1 < NC) {
            int k0 = (ch + 1) * 32;
#pragma unroll
            for (int p = 0; p < 4; p++) {
                int row = srow + p * 32;
                ra[p] = *(const float4*)(A + (size_t)(m0 + row) * K + k0 + sc4);
                rb[p] = *(const float4*)(B + (size_t)(n0 + row) * K + k0 + sc4);
            }
        }

#pragma unroll
        for (int ks = 0; ks < 4; ks++) {
            uint32_t af[4][4], bf[4][2];
#pragma unroll
            for (int mt = 0; mt < 4; mt++) {
                int m = wm * 64 + mt * 16 + fr;
                af[mt][0] = As[m][ks * 8 + fc];
                af[mt][1] = As[m + 8][ks * 8 + fc];
                af[mt][2] = As[m][ks * 8 + fc + 4];
                af[mt][3] = As[m + 8][ks * 8 + fc + 4];
            }
#pragma unroll
            for (int nt = 0; nt < 4; nt++) {
                int n = wn * 32 + nt * 8 + fr;
                bf[nt][0] = Bs[n][ks * 8 + fc];
                bf[nt][1] = Bs[n][ks * 8 + fc + 4];
            }
#pragma unroll
            for (int mt = 0; mt < 4; mt++)
#pragma unroll
                for (int nt = 0; nt < 4; nt++)
                    mma_tf32(acc[mt][nt], af[mt], bf[nt]);
        }
        __syncthreads();

        if (ch + 1 < NC) {
#pragma unroll
            for (int p = 0; p < 4; p++) {
                int row = srow + p * 32;
                uint4 ta = { f2tf(ra[p].x), f2tf(ra[p].y), f2tf(ra[p].z), f2tf(ra[p].w) };
                *(uint4*)&As[row][sc4] = ta;
                uint4 tb = { f2tf(rb[p].x), f2tf(rb[p].y), f2tf(rb[p].z), f2tf(rb[p].w) };
                *(uint4*)&Bs[row][sc4] = tb;
            }
            __syncthreads();
        }
    }

    const int c2 = (lane & 3) * 2;
#pragma unroll
    for (int mt = 0; mt < 4; mt++) {
        int m = m0 + wm * 64 + mt * 16 + fr;
#pragma unroll
        for (int nt = 0; nt < 4; nt++) {
            int n = n0 + wn * 32 + nt * 8 + c2;
            float2 v0, v1;
            if (mode == 0) {
                float b0 = bias ? bias[n] : 0.f, b1 = bias ? bias[n + 1] : 0.f;
                v0 = make_float2(acc[mt][nt][0] + b0, acc[mt][nt][1] + b1);
                v1 = make_float2(acc[mt][nt][2] + b0, acc[mt][nt][3] + b1);
            } else {
                float sc = (mode == 2) ? QSC : 1.f;
                v0.x = __uint_as_float(f2tf(acc[mt][nt][0] * sc));
                v0.y = __uint_as_float(f2tf(acc[mt][nt][1] * sc));
                v1.x = __uint_as_float(f2tf(acc[mt][nt][2] * sc));
                v1.y = __uint_as_float(f2tf(acc[mt][nt][3] * sc));
            }
            *(float2*)(C + (size_t)m * N + n)       = v0;
            *(float2*)(C + (size_t)(m + 8) * N + n) = v1;
        }
    }
}

// fused QKV: blockIdx.x 0..7 -> Q (mode 2), 8..11 -> K, 12..15 -> V (mode 1)
__global__ __launch_bounds__(256)
void gemm_qkv(const float* __restrict__ x,
              const float* __restrict__ Wq, const float* __restrict__ Wk,
              const float* __restrict__ Wv,
              float* __restrict__ q, float* __restrict__ k, float* __restrict__ v)
{
    const int bx = blockIdx.x;
    const int m0 = blockIdx.y * 128;
    if (bx < 8)       gemm_body(x, Wq, nullptr, q, NH * HD,  EMB, m0, bx * 128, 2);
    else if (bx < 12) gemm_body(x, Wk, nullptr, k, NKV * HD, EMB, m0, (bx - 8) * 128, 1);
    else              gemm_body(x, Wv, nullptr, v, NKV * HD, EMB, m0, (bx - 12) * 128, 1);
}

__global__ __launch_bounds__(256)
void gemm_mma(const float* __restrict__ A, const float* __restrict__ B,
              const float* __restrict__ bias, float* __restrict__ C,
              int M, int N, int K)
{
    gemm_body(A, B, bias, C, N, K, blockIdx.y * 128, blockIdx.x * 128, 0);
}

// =====================================================================
// Flash attention (mma.sync tf32), v5: cp.async K/V double-buffered.
// Inputs in g_q/g_k/g_v are pre-rounded tf32 bits (Q pre-scaled by QSC),
// so staging is a raw async copy — no cvt, no LDG, no STS in the loop.
// 4 warps x 32 q-rows (BQ=128), BK=64.
// Ks: [key][d] stride 68 (bank 4fr+fc, conflict-free), 2 buffers
// Vs: [key][d] stride 72 (bank 8fc+fr, conflict-free), 2 buffers
// Ps: [q][*]  stride 68 (Q staging, then P)
// =====================================================================
#define LTK 68
#define LTV 72
#define LTT 68
#define NT  (SEQ / 64)

__global__ __launch_bounds__(128, 2)
void flash_mma()
{
    extern __shared__ uint32_t smf[];
    // layout (words): Ks[2][64*68], Vs[2][64*72], Ps[128*68]
    uint32_t* Ks[2] = { smf, smf + 64 * LTK };
    uint32_t* Vs[2] = { smf + 2 * 64 * LTK, smf + 2 * 64 * LTK + 64 * LTV };
    uint32_t* Ps    = smf + 2 * 64 * LTK + 2 * 64 * LTV;

    const uint32_t ks_u[2] = { smem_u32(Ks[0]), smem_u32(Ks[1]) };
    const uint32_t vs_u[2] = { smem_u32(Vs[0]), smem_u32(Vs[1]) };
    const uint32_t ps_u    = smem_u32(Ps);

    const int tid  = threadIdx.x;
    const int lane = tid & 31;
    const int wid  = tid >> 5;
    const int fr   = lane >> 2;
    const int fc   = lane & 3;

    const int q0 = blockIdx.x * 128;
    const int h  = blockIdx.y;
    const int n  = blockIdx.z;
    const int kvh = h >> 1;
    const float slope2 = exp2f(-(float)(h + 1)) * QSC;

    // ---- async copy Q tile (pre-scaled/rounded) into Ps ----
#pragma unroll
    for (int p = 0; p < 16; p++) {
        int f4 = tid + p * 128;          // 0..2047
        int qi = f4 >> 4;
        int d4 = f4 & 15;
        const float* src = g_q + (size_t)(n * SEQ + q0 + qi) * (NH * HD) + h * HD + d4 * 4;
        CP16(ps_u + (qi * LTT + d4 * 4) * 4, src);
    }
    CP_COMMIT();

    // ---- async copy KV tile 0 into buffer 0 ----
    const size_t kvrow0 = (size_t)(n * SEQ) * (NKV * HD) + kvh * HD;
#pragma unroll
    for (int p = 0; p < 8; p++) {
        int f4 = tid + p * 128;          // 0..1023
        int ki = f4 >> 4;
        int d4 = f4 & 15;
        size_t gk = kvrow0 + (size_t)ki * (NKV * HD) + d4 * 4;
        CP16(ks_u[0] + (ki * LTK + d4 * 4) * 4, g_k + gk);
        CP16(vs_u[0] + (ki * LTV + d4 * 4) * 4, g_v + gk);
    }
    CP_COMMIT();

    CP_WAIT(1);            // Q group done
    __syncthreads();

    // ---- load Q fragments (own warp rows) ----
    const int r0 = wid * 32 + fr;
    uint32_t qf0[8][4], qf1[8][4];
#pragma unroll
    for (int ks = 0; ks < 8; ks++) {
        qf0[ks][0] = Ps[r0 * LTT + ks * 8 + fc];
        qf0[ks][1] = Ps[(r0 + 8) * LTT + ks * 8 + fc];
        qf0[ks][2] = Ps[r0 * LTT + ks * 8 + fc + 4];
        qf0[ks][3] = Ps[(r0 + 8) * LTT + ks * 8 + fc + 4];
        qf1[ks][0] = Ps[(r0 + 16) * LTT + ks * 8 + fc];
        qf1[ks][1] = Ps[(r0 + 24) * LTT + ks * 8 + fc];
        qf1[ks][2] = Ps[(r0 + 16) * LTT + ks * 8 + fc + 4];
        qf1[ks][3] = Ps[(r0 + 24) * LTT + ks * 8 + fc + 4];
    }

    float o0[8][4], o1[8][4];
#pragma unroll
    for (int nt = 0; nt < 8; nt++)
#pragma unroll
        for (int i = 0; i < 4; i++) { o0[nt][i] = 0.f; o1[nt][i] = 0.f; }
    float m00 = -INFINITY, m01 = -INFINITY, m10 = -INFINITY, m11 = -INFINITY;
    float l00 = 0.f, l01 = 0.f, l10 = 0.f, l11 = 0.f;

    const float gq0 = (float)(q0 + wid * 32 + fr);

    for (int kb = 0; kb < NT; kb++) {
        const int buf = kb & 1;

        // prefetch next KV tile into the other buffer (WAR-safe: end-sync of
        // iter kb-1 guarantees everyone finished reading it)
        if (kb + 1 < NT) {
            const size_t base = kvrow0 + (size_t)((kb + 1) * 64) * (NKV * HD);
#pragma unroll
            for (int p = 0; p < 8; p++) {
                int f4 = tid + p * 128;
                int ki = f4 >> 4;
                int d4 = f4 & 15;
                size_t gk = base + (size_t)ki * (NKV * HD) + d4 * 4;
                CP16(ks_u[buf ^ 1] + (ki * LTK + d4 * 4) * 4, g_k + gk);
                CP16(vs_u[buf ^ 1] + (ki * LTV + d4 * 4) * 4, g_v + gk);
            }
            CP_COMMIT();
            CP_WAIT(1);    // tile kb complete (own copies)
        } else {
            CP_WAIT(0);
        }
        __syncthreads();   // tile kb visible to all warps

        const uint32_t* K_ = Ks[buf];
        const uint32_t* V_ = Vs[buf];

        // ---- S = Q @ K^T ----
        float s0[8][4], s1[8][4];
#pragma unroll
        for (int nt = 0; nt < 8; nt++)
#pragma unroll
            for (int i = 0; i < 4; i++) { s0[nt][i] = 0.f; s1[nt][i] = 0.f; }

#pragma unroll
        for (int ks = 0; ks < 8; ks++) {
            uint32_t bf[8][2];
#pragma unroll
            for (int nt = 0; nt < 8; nt++) {
                bf[nt][0] = K_[(nt * 8 + fr) * LTK + ks * 8 + fc];
                bf[nt][1] = K_[(nt * 8 + fr) * LTK + ks * 8 + fc + 4];
            }
#pragma unroll
            for (int nt = 0; nt < 8; nt++) {
                mma_tf32(s0[nt], qf0[ks], bf[nt]);
                mma_tf32(s1[nt], qf1[ks], bf[nt]);
            }
        }

        // ---- ALiBi (exp2 domain) ----
#pragma unroll
        for (int nt = 0; nt < 8; nt++) {
            float k0f = (float)(kb * 64 + nt * 8 + 2 * fc);
            float k1f = k0f + 1.f;
            s0[nt][0] = fmaf(-slope2, fabsf(gq0 - k0f), s0[nt][0]);
            s0[nt][1] = fmaf(-slope2, fabsf(gq0 - k1f), s0[nt][1]);
            s0[nt][2] = fmaf(-slope2, fabsf((gq0 + 8.f) - k0f), s0[nt][2]);
            s0[nt][3] = fmaf(-slope2, fabsf((gq0 + 8.f) - k1f), s0[nt][3]);
            s1[nt][0] = fmaf(-slope2, fabsf((gq0 + 16.f) - k0f), s1[nt][0]);
            s1[nt][1] = fmaf(-slope2, fabsf((gq0 + 16.f) - k1f), s1[nt][1]);
            s1[nt][2] = fmaf(-slope2, fabsf((gq0 + 24.f) - k0f), s1[nt][2]);
            s1[nt][3] = fmaf(-slope2, fabsf((gq0 + 24.f) - k1f), s1[nt][3]);
        }

        // ---- online softmax, block0 ----
        {
            float mt0 = -INFINITY, mt1 = -INFINITY;
#pragma unroll
            for (int nt = 0; nt < 8; nt++) {
                mt0 = fmaxf(mt0, fmaxf(s0[nt][0], s0[nt][1]));
                mt1 = fmaxf(mt1, fmaxf(s0[nt][2], s0[nt][3]));
            }
            mt0 = fmaxf(mt0, __shfl_xor_sync(0xffffffffu, mt0, 1));
            mt0 = fmaxf(mt0, __shfl_xor_sync(0xffffffffu, mt0, 2));
            mt1 = fmaxf(mt1, __shfl_xor_sync(0xffffffffu, mt1, 1));
            mt1 = fmaxf(mt1, __shfl_xor_sync(0xffffffffu, mt1, 2));
            float mn0 = fmaxf(m00, mt0), mn1 = fmaxf(m01, mt1);
            float c0 = exp2f(m00 - mn0), c1 = exp2f(m01 - mn1);
            m00 = mn0; m01 = mn1;
            float rs0 = 0.f, rs1 = 0.f;
#pragma unroll
            for (int nt = 0; nt < 8; nt++) {
                float p0 = exp2f(s0[nt][0] - mn0);
                float p1 = exp2f(s0[nt][1] - mn0);
                float p2 = exp2f(s0[nt][2] - mn1);
                float p3 = exp2f(s0[nt][3] - mn1);
                rs0 += p0 + p1; rs1 += p2 + p3;
                uint2 w0 = { f2tf(p0), f2tf(p1) };
                uint2 w1 = { f2tf(p2), f2tf(p3) };
                *(uint2*)&Ps[r0 * LTT + nt * 8 + 2 * fc]       = w0;
                *(uint2*)&Ps[(r0 + 8) * LTT + nt * 8 + 2 * fc] = w1;
            }
            rs0 += __shfl_xor_sync(0xffffffffu, rs0, 1);
            rs0 += __shfl_xor_sync(0xffffffffu, rs0, 2);
            rs1 += __shfl_xor_sync(0xffffffffu, rs1, 1);
            rs1 += __shfl_xor_sync(0xffffffffu, rs1, 2);
            l00 = l00 * c0 + rs0;
            l01 = l01 * c1 + rs1;
#pragma unroll
            for (int nt = 0; nt < 8; nt++) {
                o0[nt][0] *= c0; o0[nt][1] *= c0;
                o0[nt][2] *= c1; o0[nt][3] *= c1;
            }
        }
        // ---- online softmax, block1 ----
        {
            float mt0 = -INFINITY, mt1 = -INFINITY;
#pragma unroll
            for (int nt = 0; nt < 8; nt++) {
                mt0 = fmaxf(mt0, fmaxf(s1[nt][0], s1[nt][1]));
                mt1 = fmaxf(mt1, fmaxf(s1[nt][2], s1[nt][3]));
            }
            mt0 = fmaxf(mt0, __shfl_xor_sync(0xffffffffu, mt0, 1));
            mt0 = fmaxf(mt0, __shfl_xor_sync(0xffffffffu, mt0, 2));
            mt1 = fmaxf(mt1, __shfl_xor_sync(0xffffffffu, mt1, 1));
            mt1 = fmaxf(mt1, __shfl_xor_sync(0xffffffffu, mt1, 2));
            float mn0 = fmaxf(m10, mt0), mn1 = fmaxf(m11, mt1);
            float c0 = exp2f(m10 - mn0), c1 = exp2f(m11 - mn1);
            m10 = mn0; m11 = mn1;
            float rs0 = 0.f, rs1 = 0.f;
#pragma unroll
            for (int nt = 0; nt < 8; nt++) {
                float p0 = exp2f(s1[nt][0] - mn0);
                float p1 = exp2f(s1[nt][1] - mn0);
                float p2 = exp2f(s1[nt][2] - mn1);
                float p3 = exp2f(s1[nt][3] - mn1);
                rs0 += p0 + p1; rs1 += p2 + p3;
                uint2 w0 = { f2tf(p0), f2tf(p1) };
                uint2 w1 = { f2tf(p2), f2tf(p3) };
                *(uint2*)&Ps[(r0 + 16) * LTT + nt * 8 + 2 * fc] = w0;
                *(uint2*)&Ps[(r0 + 24) * LTT + nt * 8 + 2 * fc] = w1;
            }
            rs0 += __shfl_xor_sync(0xffffffffu, rs0, 1);
            rs0 += __shfl_xor_sync(0xffffffffu, rs0, 2);
            rs1 += __shfl_xor_sync(0xffffffffu, rs1, 1);
            rs1 += __shfl_xor_sync(0xffffffffu, rs1, 2);
            l10 = l10 * c0 + rs0;
            l11 = l11 * c1 + rs1;
#pragma unroll
            for (int nt = 0; nt < 8; nt++) {
                o1[nt][0] *= c0; o1[nt][1] *= c0;
                o1[nt][2] *= c1; o1[nt][3] *= c1;
            }
        }
        __syncwarp();

        // ---- O += P @ V ----
#pragma unroll
        for (int ks = 0; ks < 8; ks++) {
            uint32_t af0[4], af1[4], bf[8][2];
            af0[0] = Ps[r0 * LTT + ks * 8 + fc];
            af0[1] = Ps[(r0 + 8) * LTT + ks * 8 + fc];
            af0[2] = Ps[r0 * LTT + ks * 8 + fc + 4];
            af0[3] = Ps[(r0 + 8) * LTT + ks * 8 + fc + 4];
            af1[0] = Ps[(r0 + 16) * LTT + ks * 8 + fc];
            af1[1] = Ps[(r0 + 24) * LTT + ks * 8 + fc];
            af1[2] = Ps[(r0 + 16) * LTT + ks * 8 + fc + 4];
            af1[3] = Ps[(r0 + 24) * LTT + ks * 8 + fc + 4];
#pragma unroll
            for (int nt = 0; nt < 8; nt++) {
                bf[nt][0] = V_[(ks * 8 + fc) * LTV + nt * 8 + fr];
                bf[nt][1] = V_[(ks * 8 + fc + 4) * LTV + nt * 8 + fr];
            }
#pragma unroll
            for (int nt = 0; nt < 8; nt++) {
                mma_tf32(o0[nt], af0, bf[nt]);
                mma_tf32(o1[nt], af1, bf[nt]);
            }
        }
        __syncthreads();   // WAR: everyone done with buf before iter kb+1 overwrites buf^1... and kb+2 overwrites buf
    }

    // ---- normalize + write ----
    {
        float i00 = 1.f / l00, i01 = 1.f / l01, i10 = 1.f / l10, i11 = 1.f / l11;
        const int qr = q0 + wid * 32 + fr;
        float* b0 = g_attn + (size_t)(n * SEQ + qr) * (NH * HD) + h * HD;
        float* b1 = g_attn + (size_t)(n * SEQ + qr + 8) * (NH * HD) + h * HD;
        float* b2 = g_attn + (size_t)(n * SEQ + qr + 16) * (NH * HD) + h * HD;
        float* b3 = g_attn + (size_t)(n * SEQ + qr + 24) * (NH * HD) + h * HD;
#pragma unroll
        for (int nt = 0; nt < 8; nt++) {
            float2 w0 = { o0[nt][0] * i00, o0[nt][1] * i00 };
            float2 w1 = { o0[nt][2] * i01, o0[nt][3] * i01 };
            float2 w2 = { o1[nt][0] * i10, o1[nt][1] * i10 };
            float2 w3 = { o1[nt][2] * i11, o1[nt][3] * i11 };
            *(float2*)(b0 + nt * 8 + 2 * fc) = w0;
            *(float2*)(b1 + nt * 8 + 2 * fc) = w1;
            *(float2*)(b2 + nt * 8 + 2 * fc) = w2;
            *(float2*)(b3 + nt * 8 + 2 * fc) = w3;
        }
    }
}

// =====================================================================
// launch
// =====================================================================
extern "C" void kernel_launch(void* const* d_in, const int* in_sizes, int n_in,
                              void* d_out, int out_size)
{
    const float* x  = (const float*)d_in[0];
    const float* Wq = (const float*)d_in[1];
    const float* Wk = (const float*)d_in[2];
    const float* Wv = (const float*)d_in[3];
    const float* Wo = (const float*)d_in[4];
    const float* bo = (const float*)d_in[5];
    float* out = (float*)d_out;

    float *qp, *kp, *vp, *ap;
    cudaGetSymbolAddress((void**)&qp, g_q);
    cudaGetSymbolAddress((void**)&kp, g_k);
    cudaGetSymbolAddress((void**)&vp, g_v);
    cudaGetSymbolAddress((void**)&ap, g_attn);

    // fused QKV projections (epilogue pre-rounds to tf32; Q pre-scaled)
    gemm_qkv<<<dim3(16, MROWS / 128), 256>>>(x, Wq, Wk, Wv, qp, kp, vp);

    // attention (cp.async double-buffered flash)
    int smemf = (2 * 64 * LTK + 2 * 64 * LTV + 128 * LTT) * (int)sizeof(uint32_t); // 106496
    cudaFuncSetAttribute(flash_mma, cudaFuncAttributeMaxDynamicSharedMemorySize, smemf);
    flash_mma<<<dim3(SEQ / 128, NH, NB), 128, smemf>>>();

    // output projection + bias
    gemm_mma<<<dim3(EMB / 128, MROWS / 128), 256>>>(ap, Wo, bo, out,
                                                    MROWS, EMB, EMB);
}

// round 9
// speedup vs baseline: 1.0648x; 1.0648x over previous
#include <cuda_runtime.h>
#include <math.h>
#include <stdint.h>

#define NB   2
#define SEQ  2048
#define EMB  1024
#define NH   16
#define NKV  8
#define HD   64
#define MROWS (NB*SEQ)   // 4096

// ---------------- scratch (no allocations allowed) ----------------
__device__ float g_q[(size_t)MROWS * NH * HD];    // 16 MB (QSC-scaled, tf32-rounded)
__device__ float g_k[(size_t)MROWS * NKV * HD];   // 8 MB  (tf32-rounded)
__device__ float g_v[(size_t)MROWS * NKV * HD];   // 8 MB  (tf32-rounded)
__device__ float g_attn[(size_t)MROWS * NH * HD]; // 16 MB

#define QSC 0.18033688011112042f   // 0.125 * log2(e)

// =====================================================================
// helpers
// =====================================================================
__device__ __forceinline__ uint32_t f2tf(float f) {
    uint32_t u;
    asm("cvt.rna.tf32.f32 %0, %1;" : "=r"(u) : "f"(f));
    return u;
}
__device__ __forceinline__ void mma_tf32(float* d, const uint32_t* a, const uint32_t* b) {
    asm volatile(
        "mma.sync.aligned.m16n8k8.row.col.f32.tf32.tf32.f32 "
        "{%0,%1,%2,%3}, {%4,%5,%6,%7}, {%8,%9}, {%0,%1,%2,%3};"
        : "+f"(d[0]), "+f"(d[1]), "+f"(d[2]), "+f"(d[3])
        : "r"(a[0]), "r"(a[1]), "r"(a[2]), "r"(a[3]), "r"(b[0]), "r"(b[1]));
}

// =====================================================================
// mma.sync tf32 GEMM body, double-buffered SMEM (dynamic).
// C[M,N] = A[M,K] @ B[N,K]^T
// mode 0: +bias fp32 out; mode 1: tf32-rounded out; mode 2: QSC*tf32 out.
// Per K-chunk(32): prefetch LDG -> compute(buf) -> store(buf^1) -> 1 sync.
// =====================================================================
#define LT 36
#define GB (128 * LT)          // words per half-buffer (As or Bs)
#define GSMEM_DYN (4 * GB * 4) // bytes: 2 buffers x (As+Bs)

__device__ __forceinline__
void gemm_body(const float* __restrict__ A, const float* __restrict__ B,
               const float* __restrict__ bias, float* __restrict__ C,
               int N, int K, int m0, int n0, int mode)
{
    extern __shared__ uint32_t gsm[];   // [2][2][128][LT] : buf, {A,B}

    const int tid  = threadIdx.x;
    const int lane = tid & 31;
    const int wid  = tid >> 5;
    const int wm   = wid >> 2;
    const int wn   = wid & 3;

    const int srow = tid >> 3;
    const int sc4  = (tid & 7) * 4;

    float acc[4][4][4];
#pragma unroll
    for (int mt = 0; mt < 4; mt++)
#pragma unroll
        for (int nt = 0; nt < 4; nt++)
#pragma unroll
            for (int i = 0; i < 4; i++) acc[mt][nt][i] = 0.f;

    float4 ra[4], rb[4];

    // prologue: load chunk 0, stage into buffer 0
#pragma unroll
    for (int p = 0; p < 4; p++) {
        int row = srow + p * 32;
        ra[p] = *(const float4*)(A + (size_t)(m0 + row) * K + sc4);
        rb[p] = *(const float4*)(B + (size_t)(n0 + row) * K + sc4);
    }
#pragma unroll
    for (int p = 0; p < 4; p++) {
        int row = srow + p * 32;
        uint4 ta = { f2tf(ra[p].x), f2tf(ra[p].y), f2tf(ra[p].z), f2tf(ra[p].w) };
        *(uint4*)&gsm[row * LT + sc4] = ta;
        uint4 tb = { f2tf(rb[p].x), f2tf(rb[p].y), f2tf(rb[p].z), f2tf(rb[p].w) };
        *(uint4*)&gsm[GB + row * LT + sc4] = tb;
    }
    __syncthreads();

    const int NC = K / 32;
    const int fr = lane >> 2;
    const int fc = lane & 3;

    for (int ch = 0; ch < NC; ch++) {
        const uint32_t* As = gsm + (ch & 1) * 2 * GB;
        const uint32_t* Bs = As + GB;

        // prefetch next chunk into registers (hidden behind mma)
        if (ch + 1 < NC) {
            int k0 = (ch + 1) * 32;
#pragma unroll
            for (int p = 0; p < 4; p++) {
                int row = srow + p * 32;
                ra[p] = *(const float4*)(A + (size_t)(m0 + row) * K + k0 + sc4);
                rb[p] = *(const float4*)(B + (size_t)(n0 + row) * K + k0 + sc4);
            }
        }

        // compute on current buffer
#pragma unroll
        for (int ks = 0; ks < 4; ks++) {
            uint32_t af[4][4], bf[4][2];
#pragma unroll
            for (int mt = 0; mt < 4; mt++) {
                int m = wm * 64 + mt * 16 + fr;
                af[mt][0] = As[m * LT + ks * 8 + fc];
                af[mt][1] = As[(m + 8) * LT + ks * 8 + fc];
                af[mt][2] = As[m * LT + ks * 8 + fc + 4];
                af[mt][3] = As[(m + 8) * LT + ks * 8 + fc + 4];
            }
#pragma unroll
            for (int nt = 0; nt < 4; nt++) {
                int n = wn * 32 + nt * 8 + fr;
                bf[nt][0] = Bs[n * LT + ks * 8 + fc];
                bf[nt][1] = Bs[n * LT + ks * 8 + fc + 4];
            }
#pragma unroll
            for (int mt = 0; mt < 4; mt++)
#pragma unroll
                for (int nt = 0; nt < 4; nt++)
                    mma_tf32(acc[mt][nt], af[mt], bf[nt]);
        }

        // stage next chunk into the other buffer (no barrier before: WAR-safe,
        // that buffer was last read in iter ch-1, which ended at a barrier)
        if (ch + 1 < NC) {
            uint32_t* An = gsm + ((ch + 1) & 1) * 2 * GB;
            uint32_t* Bn = An + GB;
#pragma unroll
            for (int p = 0; p < 4; p++) {
                int row = srow + p * 32;
                uint4 ta = { f2tf(ra[p].x), f2tf(ra[p].y), f2tf(ra[p].z), f2tf(ra[p].w) };
                *(uint4*)&An[row * LT + sc4] = ta;
                uint4 tb = { f2tf(rb[p].x), f2tf(rb[p].y), f2tf(rb[p].z), f2tf(rb[p].w) };
                *(uint4*)&Bn[row * LT + sc4] = tb;
            }
        }
        __syncthreads();
    }

    const int c2 = (lane & 3) * 2;
#pragma unroll
    for (int mt = 0; mt < 4; mt++) {
        int m = m0 + wm * 64 + mt * 16 + fr;
#pragma unroll
        for (int nt = 0; nt < 4; nt++) {
            int n = n0 + wn * 32 + nt * 8 + c2;
            float2 v0, v1;
            if (mode == 0) {
                float b0 = bias ? bias[n] : 0.f, b1 = bias ? bias[n + 1] : 0.f;
                v0 = make_float2(acc[mt][nt][0] + b0, acc[mt][nt][1] + b1);
                v1 = make_float2(acc[mt][nt][2] + b0, acc[mt][nt][3] + b1);
            } else {
                float sc = (mode == 2) ? QSC : 1.f;
                v0.x = __uint_as_float(f2tf(acc[mt][nt][0] * sc));
                v0.y = __uint_as_float(f2tf(acc[mt][nt][1] * sc));
                v1.x = __uint_as_float(f2tf(acc[mt][nt][2] * sc));
                v1.y = __uint_as_float(f2tf(acc[mt][nt][3] * sc));
            }
            *(float2*)(C + (size_t)m * N + n)       = v0;
            *(float2*)(C + (size_t)(m + 8) * N + n) = v1;
        }
    }
}

// fused QKV: blockIdx.x 0..7 -> Q (mode 2), 8..11 -> K, 12..15 -> V (mode 1)
__global__ __launch_bounds__(256)
void gemm_qkv(const float* __restrict__ x,
              const float* __restrict__ Wq, const float* __restrict__ Wk,
              const float* __restrict__ Wv,
              float* __restrict__ q, float* __restrict__ k, float* __restrict__ v)
{
    const int bx = blockIdx.x;
    const int m0 = blockIdx.y * 128;
    if (bx < 8)       gemm_body(x, Wq, nullptr, q, NH * HD,  EMB, m0, bx * 128, 2);
    else if (bx < 12) gemm_body(x, Wk, nullptr, k, NKV * HD, EMB, m0, (bx - 8) * 128, 1);
    else              gemm_body(x, Wv, nullptr, v, NKV * HD, EMB, m0, (bx - 12) * 128, 1);
}

__global__ __launch_bounds__(256)
void gemm_mma(const float* __restrict__ A, const float* __restrict__ B,
              const float* __restrict__ bias, float* __restrict__ C,
              int M, int N, int K)
{
    gemm_body(A, B, bias, C, N, K, blockIdx.y * 128, blockIdx.x * 128, 0);
}

// =====================================================================
// Flash attention (mma.sync tf32), v6 = R7 structure, pre-rounded inputs:
// staging is plain LDG+STS (L1-cached, no cvt).
// 4 warps x 32 q-rows (BQ=128), BK=64.
// Ks: [key][d] stride 68 (b-frag bank 4fr+fc, conflict-free)
// Vs: [key][d] stride 72 (b-frag bank 8fc+fr, conflict-free)
// Ps: [q][*]  stride 68 (Q staging, then P)
// =====================================================================
#define LTK 68
#define LTV 72
#define LTT 68

__global__ __launch_bounds__(128, 2)
void flash_mma()
{
    extern __shared__ uint32_t smf[];
    uint32_t* Ks = smf;                  // [64][68]
    uint32_t* Vs = Ks + 64 * LTK;        // [64][72]
    uint32_t* Ps = Vs + 64 * LTV;        // [128][68]

    const int tid  = threadIdx.x;
    const int lane = tid & 31;
    const int wid  = tid >> 5;
    const int fr   = lane >> 2;
    const int fc   = lane & 3;

    const int q0 = blockIdx.x * 128;
    const int h  = blockIdx.y;
    const int n  = blockIdx.z;
    const int kvh = h >> 1;
    const float slope2 = exp2f(-(float)(h + 1)) * QSC;

    // ---- stage Q (pre-scaled/rounded) into Ps: plain copy ----
#pragma unroll
    for (int p = 0; p < 16; p++) {
        int f4 = tid + p * 128;
        int qi = f4 >> 4;
        int d4 = f4 & 15;
        uint4 t = *(const uint4*)(g_q + (size_t)(n * SEQ + q0 + qi) * (NH * HD)
                                      + h * HD + d4 * 4);
        *(uint4*)&Ps[qi * LTT + d4 * 4] = t;
    }
    __syncthreads();

    const int r0 = wid * 32 + fr;
    uint32_t qf0[8][4], qf1[8][4];
#pragma unroll
    for (int ks = 0; ks < 8; ks++) {
        qf0[ks][0] = Ps[r0 * LTT + ks * 8 + fc];
        qf0[ks][1] = Ps[(r0 + 8) * LTT + ks * 8 + fc];
        qf0[ks][2] = Ps[r0 * LTT + ks * 8 + fc + 4];
        qf0[ks][3] = Ps[(r0 + 8) * LTT + ks * 8 + fc + 4];
        qf1[ks][0] = Ps[(r0 + 16) * LTT + ks * 8 + fc];
        qf1[ks][1] = Ps[(r0 + 24) * LTT + ks * 8 + fc];
        qf1[ks][2] = Ps[(r0 + 16) * LTT + ks * 8 + fc + 4];
        qf1[ks][3] = Ps[(r0 + 24) * LTT + ks * 8 + fc + 4];
    }

    float o0[8][4], o1[8][4];
#pragma unroll
    for (int nt = 0; nt < 8; nt++)
#pragma unroll
        for (int i = 0; i < 4; i++) { o0[nt][i] = 0.f; o1[nt][i] = 0.f; }
    float m00 = -INFINITY, m01 = -INFINITY, m10 = -INFINITY, m11 = -INFINITY;
    float l00 = 0.f, l01 = 0.f, l10 = 0.f, l11 = 0.f;

    const float gq0 = (float)(q0 + wid * 32 + fr);

    for (int kb = 0; kb < SEQ / 64; kb++) {
        __syncthreads();

        // ---- stage K and V (pre-rounded): plain LDG+STS ----
#pragma unroll
        for (int p = 0; p < 8; p++) {
            int f4 = tid + p * 128;
            int ki = f4 >> 4;
            int d4 = f4 & 15;
            size_t gk = (size_t)(n * SEQ + kb * 64 + ki) * (NKV * HD) + kvh * HD + d4 * 4;
            uint4 ta = *(const uint4*)(g_k + gk);
            *(uint4*)&Ks[ki * LTK + d4 * 4] = ta;
            uint4 tb = *(const uint4*)(g_v + gk);
            *(uint4*)&Vs[ki * LTV + d4 * 4] = tb;
        }
        __syncthreads();

        // ---- S = Q @ K^T ----
        float s0[8][4], s1[8][4];
#pragma unroll
        for (int nt = 0; nt < 8; nt++)
#pragma unroll
            for (int i = 0; i < 4; i++) { s0[nt][i] = 0.f; s1[nt][i] = 0.f; }

#pragma unroll
        for (int ks = 0; ks < 8; ks++) {
            uint32_t bf[8][2];
#pragma unroll
            for (int nt = 0; nt < 8; nt++) {
                bf[nt][0] = Ks[(nt * 8 + fr) * LTK + ks * 8 + fc];
                bf[nt][1] = Ks[(nt * 8 + fr) * LTK + ks * 8 + fc + 4];
            }
#pragma unroll
            for (int nt = 0; nt < 8; nt++) {
                mma_tf32(s0[nt], qf0[ks], bf[nt]);
                mma_tf32(s1[nt], qf1[ks], bf[nt]);
            }
        }

        // ---- ALiBi (exp2 domain) ----
#pragma unroll
        for (int nt = 0; nt < 8; nt++) {
            float k0f = (float)(kb * 64 + nt * 8 + 2 * fc);
            float k1f = k0f + 1.f;
            s0[nt][0] = fmaf(-slope2, fabsf(gq0 - k0f), s0[nt][0]);
            s0[nt][1] = fmaf(-slope2, fabsf(gq0 - k1f), s0[nt][1]);
            s0[nt][2] = fmaf(-slope2, fabsf((gq0 + 8.f) - k0f), s0[nt][2]);
            s0[nt][3] = fmaf(-slope2, fabsf((gq0 + 8.f) - k1f), s0[nt][3]);
            s1[nt][0] = fmaf(-slope2, fabsf((gq0 + 16.f) - k0f), s1[nt][0]);
            s1[nt][1] = fmaf(-slope2, fabsf((gq0 + 16.f) - k1f), s1[nt][1]);
            s1[nt][2] = fmaf(-slope2, fabsf((gq0 + 24.f) - k0f), s1[nt][2]);
            s1[nt][3] = fmaf(-slope2, fabsf((gq0 + 24.f) - k1f), s1[nt][3]);
        }

        // ---- online softmax, block0 ----
        {
            float mt0 = -INFINITY, mt1 = -INFINITY;
#pragma unroll
            for (int nt = 0; nt < 8; nt++) {
                mt0 = fmaxf(mt0, fmaxf(s0[nt][0], s0[nt][1]));
                mt1 = fmaxf(mt1, fmaxf(s0[nt][2], s0[nt][3]));
            }
            mt0 = fmaxf(mt0, __shfl_xor_sync(0xffffffffu, mt0, 1));
            mt0 = fmaxf(mt0, __shfl_xor_sync(0xffffffffu, mt0, 2));
            mt1 = fmaxf(mt1, __shfl_xor_sync(0xffffffffu, mt1, 1));
            mt1 = fmaxf(mt1, __shfl_xor_sync(0xffffffffu, mt1, 2));
            float mn0 = fmaxf(m00, mt0), mn1 = fmaxf(m01, mt1);
            float c0 = exp2f(m00 - mn0), c1 = exp2f(m01 - mn1);
            m00 = mn0; m01 = mn1;
            float rs0 = 0.f, rs1 = 0.f;
#pragma unroll
            for (int nt = 0; nt < 8; nt++) {
                float p0 = exp2f(s0[nt][0] - mn0);
                float p1 = exp2f(s0[nt][1] - mn0);
                float p2 = exp2f(s0[nt][2] - mn1);
                float p3 = exp2f(s0[nt][3] - mn1);
                rs0 += p0 + p1; rs1 += p2 + p3;
                uint2 w0 = { f2tf(p0), f2tf(p1) };
                uint2 w1 = { f2tf(p2), f2tf(p3) };
                *(uint2*)&Ps[r0 * LTT + nt * 8 + 2 * fc]       = w0;
                *(uint2*)&Ps[(r0 + 8) * LTT + nt * 8 + 2 * fc] = w1;
            }
            rs0 += __shfl_xor_sync(0xffffffffu, rs0, 1);
            rs0 += __shfl_xor_sync(0xffffffffu, rs0, 2);
            rs1 += __shfl_xor_sync(0xffffffffu, rs1, 1);
            rs1 += __shfl_xor_sync(0xffffffffu, rs1, 2);
            l00 = l00 * c0 + rs0;
            l01 = l01 * c1 + rs1;
#pragma unroll
            for (int nt = 0; nt < 8; nt++) {
                o0[nt][0] *= c0; o0[nt][1] *= c0;
                o0[nt][2] *= c1; o0[nt][3] *= c1;
            }
        }
        // ---- online softmax, block1 ----
        {
            float mt0 = -INFINITY, mt1 = -INFINITY;
#pragma unroll
            for (int nt = 0; nt < 8; nt++) {
                mt0 = fmaxf(mt0, fmaxf(s1[nt][0], s1[nt][1]));
                mt1 = fmaxf(mt1, fmaxf(s1[nt][2], s1[nt][3]));
            }
            mt0 = fmaxf(mt0, __shfl_xor_sync(0xffffffffu, mt0, 1));
            mt0 = fmaxf(mt0, __shfl_xor_sync(0xffffffffu, mt0, 2));
            mt1 = fmaxf(mt1, __shfl_xor_sync(0xffffffffu, mt1, 1));
            mt1 = fmaxf(mt1, __shfl_xor_sync(0xffffffffu, mt1, 2));
            float mn0 = fmaxf(m10, mt0), mn1 = fmaxf(m11, mt1);
            float c0 = exp2f(m10 - mn0), c1 = exp2f(m11 - mn1);
            m10 = mn0; m11 = mn1;
            float rs0 = 0.f, rs1 = 0.f;
#pragma unroll
            for (int nt = 0; nt < 8; nt++) {
                float p0 = exp2f(s1[nt][0] - mn0);
                float p1 = exp2f(s1[nt][1] - mn0);
                float p2 = exp2f(s1[nt][2] - mn1);
                float p3 = exp2f(s1[nt][3] - mn1);
                rs0 += p0 + p1; rs1 += p2 + p3;
                uint2 w0 = { f2tf(p0), f2tf(p1) };
                uint2 w1 = { f2tf(p2), f2tf(p3) };
                *(uint2*)&Ps[(r0 + 16) * LTT + nt * 8 + 2 * fc] = w0;
                *(uint2*)&Ps[(r0 + 24) * LTT + nt * 8 + 2 * fc] = w1;
            }
            rs0 += __shfl_xor_sync(0xffffffffu, rs0, 1);
            rs0 += __shfl_xor_sync(0xffffffffu, rs0, 2);
            rs1 += __shfl_xor_sync(0xffffffffu, rs1, 1);
            rs1 += __shfl_xor_sync(0xffffffffu, rs1, 2);
            l10 = l10 * c0 + rs0;
            l11 = l11 * c1 + rs1;
#pragma unroll
            for (int nt = 0; nt < 8; nt++) {
                o1[nt][0] *= c0; o1[nt][1] *= c0;
                o1[nt][2] *= c1; o1[nt][3] *= c1;
            }
        }
        __syncwarp();

        // ---- O += P @ V ----
#pragma unroll
        for (int ks = 0; ks < 8; ks++) {
            uint32_t af0[4], af1[4], bf[8][2];
            af0[0] = Ps[r0 * LTT + ks * 8 + fc];
            af0[1] = Ps[(r0 + 8) * LTT + ks * 8 + fc];
            af0[2] = Ps[r0 * LTT + ks * 8 + fc + 4];
            af0[3] = Ps[(r0 + 8) * LTT + ks * 8 + fc + 4];
            af1[0] = Ps[(r0 + 16) * LTT + ks * 8 + fc];
            af1[1] = Ps[(r0 + 24) * LTT + ks * 8 + fc];
            af1[2] = Ps[(r0 + 16) * LTT + ks * 8 + fc + 4];
            af1[3] = Ps[(r0 + 24) * LTT + ks * 8 + fc + 4];
#pragma unroll
            for (int nt = 0; nt < 8; nt++) {
                bf[nt][0] = Vs[(ks * 8 + fc) * LTV + nt * 8 + fr];
                bf[nt][1] = Vs[(ks * 8 + fc + 4) * LTV + nt * 8 + fr];
            }
#pragma unroll
            for (int nt = 0; nt < 8; nt++) {
                mma_tf32(o0[nt], af0, bf[nt]);
                mma_tf32(o1[nt], af1, bf[nt]);
            }
        }
    }

    // ---- normalize + write ----
    {
        float i00 = 1.f / l00, i01 = 1.f / l01, i10 = 1.f / l10, i11 = 1.f / l11;
        const int qr = q0 + wid * 32 + fr;
        float* b0 = g_attn + (size_t)(n * SEQ + qr) * (NH * HD) + h * HD;
        float* b1 = g_attn + (size_t)(n * SEQ + qr + 8) * (NH * HD) + h * HD;
        float* b2 = g_attn + (size_t)(n * SEQ + qr + 16) * (NH * HD) + h * HD;
        float* b3 = g_attn + (size_t)(n * SEQ + qr + 24) * (NH * HD) + h * HD;
#pragma unroll
        for (int nt = 0; nt < 8; nt++) {
            float2 w0 = { o0[nt][0] * i00, o0[nt][1] * i00 };
            float2 w1 = { o0[nt][2] * i01, o0[nt][3] * i01 };
            float2 w2 = { o1[nt][0] * i10, o1[nt][1] * i10 };
            float2 w3 = { o1[nt][2] * i11, o1[nt][3] * i11 };
            *(float2*)(b0 + nt * 8 + 2 * fc) = w0;
            *(float2*)(b1 + nt * 8 + 2 * fc) = w1;
            *(float2*)(b2 + nt * 8 + 2 * fc) = w2;
            *(float2*)(b3 + nt * 8 + 2 * fc) = w3;
        }
    }
}

// =====================================================================
// launch
// =====================================================================
extern "C" void kernel_launch(void* const* d_in, const int* in_sizes, int n_in,
                              void* d_out, int out_size)
{
    const float* x  = (const float*)d_in[0];
    const float* Wq = (const float*)d_in[1];
    const float* Wk = (const float*)d_in[2];
    const float* Wv = (const float*)d_in[3];
    const float* Wo = (const float*)d_in[4];
    const float* bo = (const float*)d_in[5];
    float* out = (float*)d_out;

    float *qp, *kp, *vp, *ap;
    cudaGetSymbolAddress((void**)&qp, g_q);
    cudaGetSymbolAddress((void**)&kp, g_k);
    cudaGetSymbolAddress((void**)&vp, g_v);
    cudaGetSymbolAddress((void**)&ap, g_attn);

    cudaFuncSetAttribute(gemm_qkv, cudaFuncAttributeMaxDynamicSharedMemorySize, GSMEM_DYN);
    cudaFuncSetAttribute(gemm_mma, cudaFuncAttributeMaxDynamicSharedMemorySize, GSMEM_DYN);

    // fused QKV projections (double-buffered; epilogue pre-rounds to tf32)
    gemm_qkv<<<dim3(16, MROWS / 128), 256, GSMEM_DYN>>>(x, Wq, Wk, Wv, qp, kp, vp);

    // attention (LDG+STS staging on pre-rounded inputs)
    int smemf = (64 * LTK + 64 * LTV + 128 * LTT) * (int)sizeof(uint32_t);  // 70656
    cudaFuncSetAttribute(flash_mma, cudaFuncAttributeMaxDynamicSharedMemorySize, smemf);
    flash_mma<<<dim3(SEQ / 128, NH, NB), 128, smemf>>>();

    // output projection + bias (double-buffered)
    gemm_mma<<<dim3(EMB / 128, MROWS / 128), 256, GSMEM_DYN>>>(ap, Wo, bo, out,
                                                               MROWS, EMB, EMB);
}

// round 10
// speedup vs baseline: 1.0954x; 1.0287x over previous
#include <cuda_runtime.h>
#include <math.h>
#include <stdint.h>

#define NB   2
#define SEQ  2048
#define EMB  1024
#define NH   16
#define NKV  8
#define HD   64
#define MROWS (NB*SEQ)   // 4096

// ---------------- scratch (no allocations allowed) ----------------
__device__ float g_q[(size_t)MROWS * NH * HD];    // QSC-scaled, tf32-rounded
__device__ float g_k[(size_t)MROWS * NKV * HD];   // tf32-rounded
__device__ float g_v[(size_t)MROWS * NKV * HD];   // tf32-rounded
__device__ float g_attn[(size_t)MROWS * NH * HD]; // tf32-rounded (flash epilogue)
__device__ float g_xt[(size_t)MROWS * EMB];       // tf32-rounded x
__device__ float g_wq[(size_t)NH * HD * EMB];     // tf32-rounded weights
__device__ float g_wk[(size_t)NKV * HD * EMB];
__device__ float g_wv[(size_t)NKV * HD * EMB];
__device__ float g_wo[(size_t)EMB * NH * HD];

#define QSC 0.18033688011112042f   // 0.125 * log2(e)

// =====================================================================
// helpers
// =====================================================================
__device__ __forceinline__ uint32_t f2tf(float f) {
    uint32_t u;
    asm("cvt.rna.tf32.f32 %0, %1;" : "=r"(u) : "f"(f));
    return u;
}
__device__ __forceinline__ void mma_tf32(float* d, const uint32_t* a, const uint32_t* b) {
    asm volatile(
        "mma.sync.aligned.m16n8k8.row.col.f32.tf32.tf32.f32 "
        "{%0,%1,%2,%3}, {%4,%5,%6,%7}, {%8,%9}, {%0,%1,%2,%3};"
        : "+f"(d[0]), "+f"(d[1]), "+f"(d[2]), "+f"(d[3])
        : "r"(a[0]), "r"(a[1]), "r"(a[2]), "r"(a[3]), "r"(b[0]), "r"(b[1]));
}
__device__ __forceinline__ uint32_t smem_u32(const void* p) {
    uint32_t a;
    asm("{ .reg .u64 t; cvta.to.shared.u64 t, %1; cvt.u32.u64 %0, t; }" : "=r"(a) : "l"(p));
    return a;
}
#define CPCA16(dst, src) \
    asm volatile("cp.async.ca.shared.global [%0], [%1], 16;" :: "r"(dst), "l"(src))
#define CP_COMMIT() asm volatile("cp.async.commit_group;" ::: "memory")
#define CP_WAIT(n)  asm volatile("cp.async.wait_group %0;" :: "n"(n) : "memory")

// =====================================================================
// pre-round: x and all weights -> tf32 scratch (one pass)
// =====================================================================
#define X4  (MROWS * EMB / 4)            // 1048576
#define WQ4 (NH * HD * EMB / 4)          // 262144
#define WK4 (NKV * HD * EMB / 4)         // 131072
#define TOT4 (X4 + WQ4 + 2 * WK4 + WQ4)  // 1835008

__global__ __launch_bounds__(256)
void preround(const float* __restrict__ x,
              const float* __restrict__ wq, const float* __restrict__ wk,
              const float* __restrict__ wv, const float* __restrict__ wo)
{
    long i = (long)blockIdx.x * 256 + threadIdx.x;   // float4 index
    const float* src; float* dst; long base;
    if (i < X4)                       { src = x;  dst = g_xt; base = 0; }
    else if (i < X4 + WQ4)            { src = wq; dst = g_wq; base = X4; }
    else if (i < X4 + WQ4 + WK4)      { src = wk; dst = g_wk; base = X4 + WQ4; }
    else if (i < X4 + WQ4 + 2 * WK4)  { src = wv; dst = g_wv; base = X4 + WQ4 + WK4; }
    else                              { src = wo; dst = g_wo; base = X4 + WQ4 + 2 * WK4; }
    long j = (i - base) * 4;
    float4 a = *(const float4*)(src + j);
    uint4 t = { f2tf(a.x), f2tf(a.y), f2tf(a.z), f2tf(a.w) };
    *(uint4*)(dst + j) = t;
}

// =====================================================================
// mma.sync tf32 GEMM v3: 128 threads, 4 warps (2x2), warp tile 64x64,
// CTA tile 128x128, K-chunk 32, cp.async.ca double-buffered staging.
// Inputs MUST be pre-rounded tf32. mode 0: +bias fp32 out; else raw.
// =====================================================================
#define LT 36
#define ABUF (128 * LT)        // words per A (or B) half
#define TBUF (2 * ABUF)        // words per buffer
#define GSMEM_DYN (2 * TBUF * 4)   // 73728 bytes

__device__ __forceinline__
void gemm_stage(uint32_t sbase, int buf, const float* __restrict__ A,
                const float* __restrict__ B, int K, int m0, int n0, int k0, int tid)
{
    uint32_t dA = sbase + (buf * TBUF) * 4;
    uint32_t dB = dA + ABUF * 4;
#pragma unroll
    for (int p = 0; p < 8; p++) {
        int c = tid + p * 128;        // 0..1023
        int row = c >> 3;             // 0..127
        int c4  = (c & 7) * 4;        // 0..28
        CPCA16(dA + (row * LT + c4) * 4, A + (size_t)(m0 + row) * K + k0 + c4);
        CPCA16(dB + (row * LT + c4) * 4, B + (size_t)(n0 + row) * K + k0 + c4);
    }
    CP_COMMIT();
}

__device__ __forceinline__
void gemm_body(const float* __restrict__ A, const float* __restrict__ B,
               const float* __restrict__ bias, float* __restrict__ C,
               int N, int K, int m0, int n0, int mode)
{
    extern __shared__ uint32_t gsm[];
    const uint32_t sbase = smem_u32(gsm);

    const int tid  = threadIdx.x;     // 0..127
    const int lane = tid & 31;
    const int wid  = tid >> 5;        // 0..3
    const int wm   = wid >> 1;        // 0..1
    const int wn   = wid & 1;         // 0..1
    const int fr   = lane >> 2;
    const int fc   = lane & 3;

    float acc[4][8][4];
#pragma unroll
    for (int mt = 0; mt < 4; mt++)
#pragma unroll
        for (int nt = 0; nt < 8; nt++)
#pragma unroll
            for (int i = 0; i < 4; i++) acc[mt][nt][i] = 0.f;

    gemm_stage(sbase, 0, A, B, K, m0, n0, 0, tid);

    const int NC = K / 32;
    for (int ch = 0; ch < NC; ch++) {
        if (ch + 1 < NC) {
            gemm_stage(sbase, (ch + 1) & 1, A, B, K, m0, n0, (ch + 1) * 32, tid);
            CP_WAIT(1);
        } else {
            CP_WAIT(0);
        }
        __syncthreads();   // chunk ch visible

        const uint32_t* As = gsm + (ch & 1) * TBUF;
        const uint32_t* Bs = As + ABUF;

#pragma unroll
        for (int ks = 0; ks < 4; ks++) {
            uint32_t af[4][4], bf[8][2];
#pragma unroll
            for (int mt = 0; mt < 4; mt++) {
                int m = wm * 64 + mt * 16 + fr;
                af[mt][0] = As[m * LT + ks * 8 + fc];
                af[mt][1] = As[(m + 8) * LT + ks * 8 + fc];
                af[mt][2] = As[m * LT + ks * 8 + fc + 4];
                af[mt][3] = As[(m + 8) * LT + ks * 8 + fc + 4];
            }
#pragma unroll
            for (int nt = 0; nt < 8; nt++) {
                int n = wn * 64 + nt * 8 + fr;
                bf[nt][0] = Bs[n * LT + ks * 8 + fc];
                bf[nt][1] = Bs[n * LT + ks * 8 + fc + 4];
            }
#pragma unroll
            for (int mt = 0; mt < 4; mt++)
#pragma unroll
                for (int nt = 0; nt < 8; nt++)
                    mma_tf32(acc[mt][nt], af[mt], bf[nt]);
        }
        __syncthreads();   // WAR: done reading before next-next overwrite
    }

    const int c2 = (lane & 3) * 2;
#pragma unroll
    for (int mt = 0; mt < 4; mt++) {
        int m = m0 + wm * 64 + mt * 16 + fr;
#pragma unroll
        for (int nt = 0; nt < 8; nt++) {
            int n = n0 + wn * 64 + nt * 8 + c2;
            float2 v0, v1;
            if (mode == 0) {
                float b0 = bias ? bias[n] : 0.f, b1 = bias ? bias[n + 1] : 0.f;
                v0 = make_float2(acc[mt][nt][0] + b0, acc[mt][nt][1] + b1);
                v1 = make_float2(acc[mt][nt][2] + b0, acc[mt][nt][3] + b1);
            } else {
                float sc = (mode == 2) ? QSC : 1.f;
                v0.x = __uint_as_float(f2tf(acc[mt][nt][0] * sc));
                v0.y = __uint_as_float(f2tf(acc[mt][nt][1] * sc));
                v1.x = __uint_as_float(f2tf(acc[mt][nt][2] * sc));
                v1.y = __uint_as_float(f2tf(acc[mt][nt][3] * sc));
            }
            *(float2*)(C + (size_t)m * N + n)       = v0;
            *(float2*)(C + (size_t)(m + 8) * N + n) = v1;
        }
    }
}

// fused QKV: blockIdx.x 0..7 -> Q (mode 2), 8..11 -> K, 12..15 -> V (mode 1)
__global__ __launch_bounds__(128)
void gemm_qkv(float* __restrict__ q, float* __restrict__ k, float* __restrict__ v)
{
    const int bx = blockIdx.x;
    const int m0 = blockIdx.y * 128;
    if (bx < 8)       gemm_body(g_xt, g_wq, nullptr, q, NH * HD,  EMB, m0, bx * 128, 2);
    else if (bx < 12) gemm_body(g_xt, g_wk, nullptr, k, NKV * HD, EMB, m0, (bx - 8) * 128, 1);
    else              gemm_body(g_xt, g_wv, nullptr, v, NKV * HD, EMB, m0, (bx - 12) * 128, 1);
}

__global__ __launch_bounds__(128)
void gemm_out(const float* __restrict__ bias, float* __restrict__ C)
{
    gemm_body(g_attn, g_wo, bias, C, EMB, EMB, blockIdx.y * 128, blockIdx.x * 128, 0);
}

// =====================================================================
// Flash attention (mma.sync tf32) — R9 structure; epilogue now writes
// tf32-rounded g_attn so out-proj can cp.async it directly.
// =====================================================================
#define LTK 68
#define LTV 72
#define LTT 68

__global__ __launch_bounds__(128, 2)
void flash_mma()
{
    extern __shared__ uint32_t smf[];
    uint32_t* Ks = smf;                  // [64][68]
    uint32_t* Vs = Ks + 64 * LTK;        // [64][72]
    uint32_t* Ps = Vs + 64 * LTV;        // [128][68]

    const int tid  = threadIdx.x;
    const int lane = tid & 31;
    const int wid  = tid >> 5;
    const int fr   = lane >> 2;
    const int fc   = lane & 3;

    const int q0 = blockIdx.x * 128;
    const int h  = blockIdx.y;
    const int n  = blockIdx.z;
    const int kvh = h >> 1;
    const float slope2 = exp2f(-(float)(h + 1)) * QSC;

    // ---- stage Q (pre-scaled/rounded): plain copy ----
#pragma unroll
    for (int p = 0; p < 16; p++) {
        int f4 = tid + p * 128;
        int qi = f4 >> 4;
        int d4 = f4 & 15;
        uint4 t = *(const uint4*)(g_q + (size_t)(n * SEQ + q0 + qi) * (NH * HD)
                                      + h * HD + d4 * 4);
        *(uint4*)&Ps[qi * LTT + d4 * 4] = t;
    }
    __syncthreads();

    const int r0 = wid * 32 + fr;
    uint32_t qf0[8][4], qf1[8][4];
#pragma unroll
    for (int ks = 0; ks < 8; ks++) {
        qf0[ks][0] = Ps[r0 * LTT + ks * 8 + fc];
        qf0[ks][1] = Ps[(r0 + 8) * LTT + ks * 8 + fc];
        qf0[ks][2] = Ps[r0 * LTT + ks * 8 + fc + 4];
        qf0[ks][3] = Ps[(r0 + 8) * LTT + ks * 8 + fc + 4];
        qf1[ks][0] = Ps[(r0 + 16) * LTT + ks * 8 + fc];
        qf1[ks][1] = Ps[(r0 + 24) * LTT + ks * 8 + fc];
        qf1[ks][2] = Ps[(r0 + 16) * LTT + ks * 8 + fc + 4];
        qf1[ks][3] = Ps[(r0 + 24) * LTT + ks * 8 + fc + 4];
    }

    float o0[8][4], o1[8][4];
#pragma unroll
    for (int nt = 0; nt < 8; nt++)
#pragma unroll
        for (int i = 0; i < 4; i++) { o0[nt][i] = 0.f; o1[nt][i] = 0.f; }
    float m00 = -INFINITY, m01 = -INFINITY, m10 = -INFINITY, m11 = -INFINITY;
    float l00 = 0.f, l01 = 0.f, l10 = 0.f, l11 = 0.f;

    const float gq0 = (float)(q0 + wid * 32 + fr);

    for (int kb = 0; kb < SEQ / 64; kb++) {
        __syncthreads();

        // ---- stage K and V (pre-rounded): plain LDG+STS ----
#pragma unroll
        for (int p = 0; p < 8; p++) {
            int f4 = tid + p * 128;
            int ki = f4 >> 4;
            int d4 = f4 & 15;
            size_t gk = (size_t)(n * SEQ + kb * 64 + ki) * (NKV * HD) + kvh * HD + d4 * 4;
            uint4 ta = *(const uint4*)(g_k + gk);
            *(uint4*)&Ks[ki * LTK + d4 * 4] = ta;
            uint4 tb = *(const uint4*)(g_v + gk);
            *(uint4*)&Vs[ki * LTV + d4 * 4] = tb;
        }
        __syncthreads();

        // ---- S = Q @ K^T ----
        float s0[8][4], s1[8][4];
#pragma unroll
        for (int nt = 0; nt < 8; nt++)
#pragma unroll
            for (int i = 0; i < 4; i++) { s0[nt][i] = 0.f; s1[nt][i] = 0.f; }

#pragma unroll
        for (int ks = 0; ks < 8; ks++) {
            uint32_t bf[8][2];
#pragma unroll
            for (int nt = 0; nt < 8; nt++) {
                bf[nt][0] = Ks[(nt * 8 + fr) * LTK + ks * 8 + fc];
                bf[nt][1] = Ks[(nt * 8 + fr) * LTK + ks * 8 + fc + 4];
            }
#pragma unroll
            for (int nt = 0; nt < 8; nt++) {
                mma_tf32(s0[nt], qf0[ks], bf[nt]);
                mma_tf32(s1[nt], qf1[ks], bf[nt]);
            }
        }

        // ---- ALiBi (exp2 domain) ----
#pragma unroll
        for (int nt = 0; nt < 8; nt++) {
            float k0f = (float)(kb * 64 + nt * 8 + 2 * fc);
            float k1f = k0f + 1.f;
            s0[nt][0] = fmaf(-slope2, fabsf(gq0 - k0f), s0[nt][0]);
            s0[nt][1] = fmaf(-slope2, fabsf(gq0 - k1f), s0[nt][1]);
            s0[nt][2] = fmaf(-slope2, fabsf((gq0 + 8.f) - k0f), s0[nt][2]);
            s0[nt][3] = fmaf(-slope2, fabsf((gq0 + 8.f) - k1f), s0[nt][3]);
            s1[nt][0] = fmaf(-slope2, fabsf((gq0 + 16.f) - k0f), s1[nt][0]);
            s1[nt][1] = fmaf(-slope2, fabsf((gq0 + 16.f) - k1f), s1[nt][1]);
            s1[nt][2] = fmaf(-slope2, fabsf((gq0 + 24.f) - k0f), s1[nt][2]);
            s1[nt][3] = fmaf(-slope2, fabsf((gq0 + 24.f) - k1f), s1[nt][3]);
        }

        // ---- online softmax, block0 ----
        {
            float mt0 = -INFINITY, mt1 = -INFINITY;
#pragma unroll
            for (int nt = 0; nt < 8; nt++) {
                mt0 = fmaxf(mt0, fmaxf(s0[nt][0], s0[nt][1]));
                mt1 = fmaxf(mt1, fmaxf(s0[nt][2], s0[nt][3]));
            }
            mt0 = fmaxf(mt0, __shfl_xor_sync(0xffffffffu, mt0, 1));
            mt0 = fmaxf(mt0, __shfl_xor_sync(0xffffffffu, mt0, 2));
            mt1 = fmaxf(mt1, __shfl_xor_sync(0xffffffffu, mt1, 1));
            mt1 = fmaxf(mt1, __shfl_xor_sync(0xffffffffu, mt1, 2));
            float mn0 = fmaxf(m00, mt0), mn1 = fmaxf(m01, mt1);
            float c0 = exp2f(m00 - mn0), c1 = exp2f(m01 - mn1);
            m00 = mn0; m01 = mn1;
            float rs0 = 0.f, rs1 = 0.f;
#pragma unroll
            for (int nt = 0; nt < 8; nt++) {
                float p0 = exp2f(s0[nt][0] - mn0);
                float p1 = exp2f(s0[nt][1] - mn0);
                float p2 = exp2f(s0[nt][2] - mn1);
                float p3 = exp2f(s0[nt][3] - mn1);
                rs0 += p0 + p1; rs1 += p2 + p3;
                uint2 w0 = { f2tf(p0), f2tf(p1) };
                uint2 w1 = { f2tf(p2), f2tf(p3) };
                *(uint2*)&Ps[r0 * LTT + nt * 8 + 2 * fc]       = w0;
                *(uint2*)&Ps[(r0 + 8) * LTT + nt * 8 + 2 * fc] = w1;
            }
            rs0 += __shfl_xor_sync(0xffffffffu, rs0, 1);
            rs0 += __shfl_xor_sync(0xffffffffu, rs0, 2);
            rs1 += __shfl_xor_sync(0xffffffffu, rs1, 1);
            rs1 += __shfl_xor_sync(0xffffffffu, rs1, 2);
            l00 = l00 * c0 + rs0;
            l01 = l01 * c1 + rs1;
#pragma unroll
            for (int nt = 0; nt < 8; nt++) {
                o0[nt][0] *= c0; o0[nt][1] *= c0;
                o0[nt][2] *= c1; o0[nt][3] *= c1;
            }
        }
        // ---- online softmax, block1 ----
        {
            float mt0 = -INFINITY, mt1 = -INFINITY;
#pragma unroll
            for (int nt = 0; nt < 8; nt++) {
                mt0 = fmaxf(mt0, fmaxf(s1[nt][0], s1[nt][1]));
                mt1 = fmaxf(mt1, fmaxf(s1[nt][2], s1[nt][3]));
            }
            mt0 = fmaxf(mt0, __shfl_xor_sync(0xffffffffu, mt0, 1));
            mt0 = fmaxf(mt0, __shfl_xor_sync(0xffffffffu, mt0, 2));
            mt1 = fmaxf(mt1, __shfl_xor_sync(0xffffffffu, mt1, 1));
            mt1 = fmaxf(mt1, __shfl_xor_sync(0xffffffffu, mt1, 2));
            float mn0 = fmaxf(m10, mt0), mn1 = fmaxf(m11, mt1);
            float c0 = exp2f(m10 - mn0), c1 = exp2f(m11 - mn1);
            m10 = mn0; m11 = mn1;
            float rs0 = 0.f, rs1 = 0.f;
#pragma unroll
            for (int nt = 0; nt < 8; nt++) {
                float p0 = exp2f(s1[nt][0] - mn0);
                float p1 = exp2f(s1[nt][1] - mn0);
                float p2 = exp2f(s1[nt][2] - mn1);
                float p3 = exp2f(s1[nt][3] - mn1);
                rs0 += p0 + p1; rs1 += p2 + p3;
                uint2 w0 = { f2tf(p0), f2tf(p1) };
                uint2 w1 = { f2tf(p2), f2tf(p3) };
                *(uint2*)&Ps[(r0 + 16) * LTT + nt * 8 + 2 * fc] = w0;
                *(uint2*)&Ps[(r0 + 24) * LTT + nt * 8 + 2 * fc] = w1;
            }
            rs0 += __shfl_xor_sync(0xffffffffu, rs0, 1);
            rs0 += __shfl_xor_sync(0xffffffffu, rs0, 2);
            rs1 += __shfl_xor_sync(0xffffffffu, rs1, 1);
            rs1 += __shfl_xor_sync(0xffffffffu, rs1, 2);
            l10 = l10 * c0 + rs0;
            l11 = l11 * c1 + rs1;
#pragma unroll
            for (int nt = 0; nt < 8; nt++) {
                o1[nt][0] *= c0; o1[nt][1] *= c0;
                o1[nt][2] *= c1; o1[nt][3] *= c1;
            }
        }
        __syncwarp();

        // ---- O += P @ V ----
#pragma unroll
        for (int ks = 0; ks < 8; ks++) {
            uint32_t af0[4], af1[4], bf[8][2];
            af0[0] = Ps[r0 * LTT + ks * 8 + fc];
            af0[1] = Ps[(r0 + 8) * LTT + ks * 8 + fc];
            af0[2] = Ps[r0 * LTT + ks * 8 + fc + 4];
            af0[3] = Ps[(r0 + 8) * LTT + ks * 8 + fc + 4];
            af1[0] = Ps[(r0 + 16) * LTT + ks * 8 + fc];
            af1[1] = Ps[(r0 + 24) * LTT + ks * 8 + fc];
            af1[2] = Ps[(r0 + 16) * LTT + ks * 8 + fc + 4];
            af1[3] = Ps[(r0 + 24) * LTT + ks * 8 + fc + 4];
#pragma unroll
            for (int nt = 0; nt < 8; nt++) {
                bf[nt][0] = Vs[(ks * 8 + fc) * LTV + nt * 8 + fr];
                bf[nt][1] = Vs[(ks * 8 + fc + 4) * LTV + nt * 8 + fr];
            }
#pragma unroll
            for (int nt = 0; nt < 8; nt++) {
                mma_tf32(o0[nt], af0, bf[nt]);
                mma_tf32(o1[nt], af1, bf[nt]);
            }
        }
    }

    // ---- normalize + write (tf32-rounded for out-proj cp.async) ----
    {
        float i00 = 1.f / l00, i01 = 1.f / l01, i10 = 1.f / l10, i11 = 1.f / l11;
        const int qr = q0 + wid * 32 + fr;
        float* b0 = g_attn + (size_t)(n * SEQ + qr) * (NH * HD) + h * HD;
        float* b1 = g_attn + (size_t)(n * SEQ + qr + 8) * (NH * HD) + h * HD;
        float* b2 = g_attn + (size_t)(n * SEQ + qr + 16) * (NH * HD) + h * HD;
        float* b3 = g_attn + (size_t)(n * SEQ + qr + 24) * (NH * HD) + h * HD;
#pragma unroll
        for (int nt = 0; nt < 8; nt++) {
            uint2 w0 = { f2tf(o0[nt][0] * i00), f2tf(o0[nt][1] * i00) };
            uint2 w1 = { f2tf(o0[nt][2] * i01), f2tf(o0[nt][3] * i01) };
            uint2 w2 = { f2tf(o1[nt][0] * i10), f2tf(o1[nt][1] * i10) };
            uint2 w3 = { f2tf(o1[nt][2] * i11), f2tf(o1[nt][3] * i11) };
            *(uint2*)(b0 + nt * 8 + 2 * fc) = w0;
            *(uint2*)(b1 + nt * 8 + 2 * fc) = w1;
            *(uint2*)(b2 + nt * 8 + 2 * fc) = w2;
            *(uint2*)(b3 + nt * 8 + 2 * fc) = w3;
        }
    }
}

// =====================================================================
// launch
// =====================================================================
extern "C" void kernel_launch(void* const* d_in, const int* in_sizes, int n_in,
                              void* d_out, int out_size)
{
    const float* x  = (const float*)d_in[0];
    const float* Wq = (const float*)d_in[1];
    const float* Wk = (const float*)d_in[2];
    const float* Wv = (const float*)d_in[3];
    const float* Wo = (const float*)d_in[4];
    const float* bo = (const float*)d_in[5];
    float* out = (float*)d_out;

    float *qp, *kp, *vp;
    cudaGetSymbolAddress((void**)&qp, g_q);
    cudaGetSymbolAddress((void**)&kp, g_k);
    cudaGetSymbolAddress((void**)&vp, g_v);

    // pre-round x + weights to tf32 scratch
    preround<<<TOT4 / 256, 256>>>(x, Wq, Wk, Wv, Wo);

    cudaFuncSetAttribute(gemm_qkv, cudaFuncAttributeMaxDynamicSharedMemorySize, GSMEM_DYN);
    cudaFuncSetAttribute(gemm_out, cudaFuncAttributeMaxDynamicSharedMemorySize, GSMEM_DYN);

    // fused QKV projections
    gemm_qkv<<<dim3(16, MROWS / 128), 128, GSMEM_DYN>>>(qp, kp, vp);

    // attention
    int smemf = (64 * LTK + 64 * LTV + 128 * LTT) * (int)sizeof(uint32_t);  // 70656
    cudaFuncSetAttribute(flash_mma, cudaFuncAttributeMaxDynamicSharedMemorySize, smemf);
    flash_mma<<<dim3(SEQ / 128, NH, NB), 128, smemf>>>();

    // output projection + bias
    gemm_out<<<dim3(EMB / 128, MROWS / 128), 128, GSMEM_DYN>>>(bo, out);
}

// round 11
// speedup vs baseline: 1.1333x; 1.0346x over previous
#include <cuda_runtime.h>
#include <math.h>
#include <stdint.h>

#define NB   2
#define SEQ  2048
#define EMB  1024
#define NH   16
#define NKV  8
#define HD   64
#define MROWS (NB*SEQ)   // 4096

// ---------------- scratch (no allocations allowed) ----------------
__device__ float g_q[(size_t)MROWS * NH * HD];    // QSC-scaled, tf32-rounded
__device__ float g_k[(size_t)MROWS * NKV * HD];   // tf32-rounded
__device__ float g_v[(size_t)MROWS * NKV * HD];   // tf32-rounded
__device__ float g_attn[(size_t)MROWS * NH * HD]; // tf32-rounded (flash epilogue)
__device__ float g_xt[(size_t)MROWS * EMB];       // tf32-rounded x
__device__ float g_wq[(size_t)NH * HD * EMB];
__device__ float g_wk[(size_t)NKV * HD * EMB];
__device__ float g_wv[(size_t)NKV * HD * EMB];
__device__ float g_wo[(size_t)EMB * NH * HD];

#define QSC 0.18033688011112042f   // 0.125 * log2(e)

// =====================================================================
// helpers
// =====================================================================
__device__ __forceinline__ uint32_t f2tf(float f) {
    uint32_t u;
    asm("cvt.rna.tf32.f32 %0, %1;" : "=r"(u) : "f"(f));
    return u;
}
__device__ __forceinline__ void mma_tf32(float* d, const uint32_t* a, const uint32_t* b) {
    asm volatile(
        "mma.sync.aligned.m16n8k8.row.col.f32.tf32.tf32.f32 "
        "{%0,%1,%2,%3}, {%4,%5,%6,%7}, {%8,%9}, {%0,%1,%2,%3};"
        : "+f"(d[0]), "+f"(d[1]), "+f"(d[2]), "+f"(d[3])
        : "r"(a[0]), "r"(a[1]), "r"(a[2]), "r"(a[3]), "r"(b[0]), "r"(b[1]));
}
__device__ __forceinline__ uint32_t smem_u32(const void* p) {
    uint32_t a;
    asm("{ .reg .u64 t; cvta.to.shared.u64 t, %1; cvt.u32.u64 %0, t; }" : "=r"(a) : "l"(p));
    return a;
}
#define CPCA16(dst, src) \
    asm volatile("cp.async.ca.shared.global [%0], [%1], 16;" :: "r"(dst), "l"(src))
#define CP_COMMIT() asm volatile("cp.async.commit_group;" ::: "memory")
#define CP_WAIT(n)  asm volatile("cp.async.wait_group %0;" :: "n"(n) : "memory")

// =====================================================================
// pre-round: x and all weights -> tf32 scratch (one pass)
// =====================================================================
#define X4  (MROWS * EMB / 4)
#define WQ4 (NH * HD * EMB / 4)
#define WK4 (NKV * HD * EMB / 4)
#define TOT4 (X4 + WQ4 + 2 * WK4 + WQ4)

__global__ __launch_bounds__(256)
void preround(const float* __restrict__ x,
              const float* __restrict__ wq, const float* __restrict__ wk,
              const float* __restrict__ wv, const float* __restrict__ wo)
{
    long i = (long)blockIdx.x * 256 + threadIdx.x;
    const float* src; float* dst; long base;
    if (i < X4)                       { src = x;  dst = g_xt; base = 0; }
    else if (i < X4 + WQ4)            { src = wq; dst = g_wq; base = X4; }
    else if (i < X4 + WQ4 + WK4)      { src = wk; dst = g_wk; base = X4 + WQ4; }
    else if (i < X4 + WQ4 + 2 * WK4)  { src = wv; dst = g_wv; base = X4 + WQ4 + WK4; }
    else                              { src = wo; dst = g_wo; base = X4 + WQ4 + 2 * WK4; }
    long j = (i - base) * 4;
    float4 a = *(const float4*)(src + j);
    uint4 t = { f2tf(a.x), f2tf(a.y), f2tf(a.z), f2tf(a.w) };
    *(uint4*)(dst + j) = t;
}

// =====================================================================
// mma.sync tf32 GEMM v4: 256 threads, 8 warps (2x4), warp tile 64x64,
// CTA tile 128x256, K-chunk 32, cp.async.ca double-buffered.
// Inputs MUST be pre-rounded tf32.
// mode 0: +bias fp32 out; mode 1: tf32 out; mode 2: QSC*tf32 out.
// =====================================================================
#define LT 36
#define ABUF (128 * LT)            // A half: 4608 words
#define BBUF (256 * LT)            // B half: 9216 words
#define TBUF (ABUF + BBUF)         // 13824 words per buffer
#define GSMEM_DYN (2 * TBUF * 4)   // 110592 bytes

__device__ __forceinline__
void gemm_stage(uint32_t sbase, int buf, const float* __restrict__ A,
                const float* __restrict__ B, int K, int m0, int n0, int k0, int tid)
{
    uint32_t dA = sbase + (buf * TBUF) * 4;
    uint32_t dB = dA + ABUF * 4;
    // A: 128 rows x 8 c4-chunks = 1024 cp16 -> 4/thread
#pragma unroll
    for (int p = 0; p < 4; p++) {
        int c = tid + p * 256;
        int row = c >> 3;
        int c4  = (c & 7) * 4;
        CPCA16(dA + (row * LT + c4) * 4, A + (size_t)(m0 + row) * K + k0 + c4);
    }
    // B: 256 rows x 8 = 2048 cp16 -> 8/thread
#pragma unroll
    for (int p = 0; p < 8; p++) {
        int c = tid + p * 256;
        int row = c >> 3;
        int c4  = (c & 7) * 4;
        CPCA16(dB + (row * LT + c4) * 4, B + (size_t)(n0 + row) * K + k0 + c4);
    }
    CP_COMMIT();
}

__device__ __forceinline__
void gemm_body(const float* __restrict__ A, const float* __restrict__ B,
               const float* __restrict__ bias, float* __restrict__ C,
               int N, int K, int m0, int n0, int mode)
{
    extern __shared__ uint32_t gsm[];
    const uint32_t sbase = smem_u32(gsm);

    const int tid  = threadIdx.x;     // 0..255
    const int lane = tid & 31;
    const int wid  = tid >> 5;        // 0..7
    const int wm   = wid >> 2;        // 0..1
    const int wn   = wid & 3;         // 0..3
    const int fr   = lane >> 2;
    const int fc   = lane & 3;

    float acc[4][8][4];
#pragma unroll
    for (int mt = 0; mt < 4; mt++)
#pragma unroll
        for (int nt = 0; nt < 8; nt++)
#pragma unroll
            for (int i = 0; i < 4; i++) acc[mt][nt][i] = 0.f;

    gemm_stage(sbase, 0, A, B, K, m0, n0, 0, tid);

    const int NC = K / 32;
    for (int ch = 0; ch < NC; ch++) {
        if (ch + 1 < NC) {
            gemm_stage(sbase, (ch + 1) & 1, A, B, K, m0, n0, (ch + 1) * 32, tid);
            CP_WAIT(1);
        } else {
            CP_WAIT(0);
        }
        __syncthreads();

        const uint32_t* As = gsm + (ch & 1) * TBUF;
        const uint32_t* Bs = As + ABUF;

#pragma unroll
        for (int ks = 0; ks < 4; ks++) {
            uint32_t af[4][4], bf[8][2];
#pragma unroll
            for (int mt = 0; mt < 4; mt++) {
                int m = wm * 64 + mt * 16 + fr;
                af[mt][0] = As[m * LT + ks * 8 + fc];
                af[mt][1] = As[(m + 8) * LT + ks * 8 + fc];
                af[mt][2] = As[m * LT + ks * 8 + fc + 4];
                af[mt][3] = As[(m + 8) * LT + ks * 8 + fc + 4];
            }
#pragma unroll
            for (int nt = 0; nt < 8; nt++) {
                int n = wn * 64 + nt * 8 + fr;
                bf[nt][0] = Bs[n * LT + ks * 8 + fc];
                bf[nt][1] = Bs[n * LT + ks * 8 + fc + 4];
            }
#pragma unroll
            for (int mt = 0; mt < 4; mt++)
#pragma unroll
                for (int nt = 0; nt < 8; nt++)
                    mma_tf32(acc[mt][nt], af[mt], bf[nt]);
        }
        __syncthreads();
    }

    const int c2 = (lane & 3) * 2;
#pragma unroll
    for (int mt = 0; mt < 4; mt++) {
        int m = m0 + wm * 64 + mt * 16 + fr;
#pragma unroll
        for (int nt = 0; nt < 8; nt++) {
            int n = n0 + wn * 64 + nt * 8 + c2;
            float2 v0, v1;
            if (mode == 0) {
                float b0 = bias ? bias[n] : 0.f, b1 = bias ? bias[n + 1] : 0.f;
                v0 = make_float2(acc[mt][nt][0] + b0, acc[mt][nt][1] + b1);
                v1 = make_float2(acc[mt][nt][2] + b0, acc[mt][nt][3] + b1);
            } else {
                float sc = (mode == 2) ? QSC : 1.f;
                v0.x = __uint_as_float(f2tf(acc[mt][nt][0] * sc));
                v0.y = __uint_as_float(f2tf(acc[mt][nt][1] * sc));
                v1.x = __uint_as_float(f2tf(acc[mt][nt][2] * sc));
                v1.y = __uint_as_float(f2tf(acc[mt][nt][3] * sc));
            }
            *(float2*)(C + (size_t)m * N + n)       = v0;
            *(float2*)(C + (size_t)(m + 8) * N + n) = v1;
        }
    }
}

// fused QKV: blockIdx.x 0..3 -> Q (N-block of 256), 4..5 -> K, 6..7 -> V
__global__ __launch_bounds__(256)
void gemm_qkv(float* __restrict__ q, float* __restrict__ k, float* __restrict__ v)
{
    const int bx = blockIdx.x;
    const int m0 = blockIdx.y * 128;
    if (bx < 4)      gemm_body(g_xt, g_wq, nullptr, q, NH * HD,  EMB, m0, bx * 256, 2);
    else if (bx < 6) gemm_body(g_xt, g_wk, nullptr, k, NKV * HD, EMB, m0, (bx - 4) * 256, 1);
    else             gemm_body(g_xt, g_wv, nullptr, v, NKV * HD, EMB, m0, (bx - 6) * 256, 1);
}

__global__ __launch_bounds__(256)
void gemm_out(const float* __restrict__ bias, float* __restrict__ C)
{
    gemm_body(g_attn, g_wo, bias, C, EMB, EMB, blockIdx.y * 128, blockIdx.x * 256, 0);
}

// =====================================================================
// Flash attention (mma.sync tf32) — unchanged from R10.
// =====================================================================
#define LTK 68
#define LTV 72
#define LTT 68

__global__ __launch_bounds__(128, 2)
void flash_mma()
{
    extern __shared__ uint32_t smf[];
    uint32_t* Ks = smf;
    uint32_t* Vs = Ks + 64 * LTK;
    uint32_t* Ps = Vs + 64 * LTV;

    const int tid  = threadIdx.x;
    const int lane = tid & 31;
    const int wid  = tid >> 5;
    const int fr   = lane >> 2;
    const int fc   = lane & 3;

    const int q0 = blockIdx.x * 128;
    const int h  = blockIdx.y;
    const int n  = blockIdx.z;
    const int kvh = h >> 1;
    const float slope2 = exp2f(-(float)(h + 1)) * QSC;

#pragma unroll
    for (int p = 0; p < 16; p++) {
        int f4 = tid + p * 128;
        int qi = f4 >> 4;
        int d4 = f4 & 15;
        uint4 t = *(const uint4*)(g_q + (size_t)(n * SEQ + q0 + qi) * (NH * HD)
                                      + h * HD + d4 * 4);
        *(uint4*)&Ps[qi * LTT + d4 * 4] = t;
    }
    __syncthreads();

    const int r0 = wid * 32 + fr;
    uint32_t qf0[8][4], qf1[8][4];
#pragma unroll
    for (int ks = 0; ks < 8; ks++) {
        qf0[ks][0] = Ps[r0 * LTT + ks * 8 + fc];
        qf0[ks][1] = Ps[(r0 + 8) * LTT + ks * 8 + fc];
        qf0[ks][2] = Ps[r0 * LTT + ks * 8 + fc + 4];
        qf0[ks][3] = Ps[(r0 + 8) * LTT + ks * 8 + fc + 4];
        qf1[ks][0] = Ps[(r0 + 16) * LTT + ks * 8 + fc];
        qf1[ks][1] = Ps[(r0 + 24) * LTT + ks * 8 + fc];
        qf1[ks][2] = Ps[(r0 + 16) * LTT + ks * 8 + fc + 4];
        qf1[ks][3] = Ps[(r0 + 24) * LTT + ks * 8 + fc + 4];
    }

    float o0[8][4], o1[8][4];
#pragma unroll
    for (int nt = 0; nt < 8; nt++)
#pragma unroll
        for (int i = 0; i < 4; i++) { o0[nt][i] = 0.f; o1[nt][i] = 0.f; }
    float m00 = -INFINITY, m01 = -INFINITY, m10 = -INFINITY, m11 = -INFINITY;
    float l00 = 0.f, l01 = 0.f, l10 = 0.f, l11 = 0.f;

    const float gq0 = (float)(q0 + wid * 32 + fr);

    for (int kb = 0; kb < SEQ / 64; kb++) {
        __syncthreads();

#pragma unroll
        for (int p = 0; p < 8; p++) {
            int f4 = tid + p * 128;
            int ki = f4 >> 4;
            int d4 = f4 & 15;
            size_t gk = (size_t)(n * SEQ + kb * 64 + ki) * (NKV * HD) + kvh * HD + d4 * 4;
            uint4 ta = *(const uint4*)(g_k + gk);
            *(uint4*)&Ks[ki * LTK + d4 * 4] = ta;
            uint4 tb = *(const uint4*)(g_v + gk);
            *(uint4*)&Vs[ki * LTV + d4 * 4] = tb;
        }
        __syncthreads();

        float s0[8][4], s1[8][4];
#pragma unroll
        for (int nt = 0; nt < 8; nt++)
#pragma unroll
            for (int i = 0; i < 4; i++) { s0[nt][i] = 0.f; s1[nt][i] = 0.f; }

#pragma unroll
        for (int ks = 0; ks < 8; ks++) {
            uint32_t bf[8][2];
#pragma unroll
            for (int nt = 0; nt < 8; nt++) {
                bf[nt][0] = Ks[(nt * 8 + fr) * LTK + ks * 8 + fc];
                bf[nt][1] = Ks[(nt * 8 + fr) * LTK + ks * 8 + fc + 4];
            }
#pragma unroll
            for (int nt = 0; nt < 8; nt++) {
                mma_tf32(s0[nt], qf0[ks], bf[nt]);
                mma_tf32(s1[nt], qf1[ks], bf[nt]);
            }
        }

#pragma unroll
        for (int nt = 0; nt < 8; nt++) {
            float k0f = (float)(kb * 64 + nt * 8 + 2 * fc);
            float k1f = k0f + 1.f;
            s0[nt][0] = fmaf(-slope2, fabsf(gq0 - k0f), s0[nt][0]);
            s0[nt][1] = fmaf(-slope2, fabsf(gq0 - k1f), s0[nt][1]);
            s0[nt][2] = fmaf(-slope2, fabsf((gq0 + 8.f) - k0f), s0[nt][2]);
            s0[nt][3] = fmaf(-slope2, fabsf((gq0 + 8.f) - k1f), s0[nt][3]);
            s1[nt][0] = fmaf(-slope2, fabsf((gq0 + 16.f) - k0f), s1[nt][0]);
            s1[nt][1] = fmaf(-slope2, fabsf((gq0 + 16.f) - k1f), s1[nt][1]);
            s1[nt][2] = fmaf(-slope2, fabsf((gq0 + 24.f) - k0f), s1[nt][2]);
            s1[nt][3] = fmaf(-slope2, fabsf((gq0 + 24.f) - k1f), s1[nt][3]);
        }

        {
            float mt0 = -INFINITY, mt1 = -INFINITY;
#pragma unroll
            for (int nt = 0; nt < 8; nt++) {
                mt0 = fmaxf(mt0, fmaxf(s0[nt][0], s0[nt][1]));
                mt1 = fmaxf(mt1, fmaxf(s0[nt][2], s0[nt][3]));
            }
            mt0 = fmaxf(mt0, __shfl_xor_sync(0xffffffffu, mt0, 1));
            mt0 = fmaxf(mt0, __shfl_xor_sync(0xffffffffu, mt0, 2));
            mt1 = fmaxf(mt1, __shfl_xor_sync(0xffffffffu, mt1, 1));
            mt1 = fmaxf(mt1, __shfl_xor_sync(0xffffffffu, mt1, 2));
            float mn0 = fmaxf(m00, mt0), mn1 = fmaxf(m01, mt1);
            float c0 = exp2f(m00 - mn0), c1 = exp2f(m01 - mn1);
            m00 = mn0; m01 = mn1;
            float rs0 = 0.f, rs1 = 0.f;
#pragma unroll
            for (int nt = 0; nt < 8; nt++) {
                float p0 = exp2f(s0[nt][0] - mn0);
                float p1 = exp2f(s0[nt][1] - mn0);
                float p2 = exp2f(s0[nt][2] - mn1);
                float p3 = exp2f(s0[nt][3] - mn1);
                rs0 += p0 + p1; rs1 += p2 + p3;
                uint2 w0 = { f2tf(p0), f2tf(p1) };
                uint2 w1 = { f2tf(p2), f2tf(p3) };
                *(uint2*)&Ps[r0 * LTT + nt * 8 + 2 * fc]       = w0;
                *(uint2*)&Ps[(r0 + 8) * LTT + nt * 8 + 2 * fc] = w1;
            }
            rs0 += __shfl_xor_sync(0xffffffffu, rs0, 1);
            rs0 += __shfl_xor_sync(0xffffffffu, rs0, 2);
            rs1 += __shfl_xor_sync(0xffffffffu, rs1, 1);
            rs1 += __shfl_xor_sync(0xffffffffu, rs1, 2);
            l00 = l00 * c0 + rs0;
            l01 = l01 * c1 + rs1;
#pragma unroll
            for (int nt = 0; nt < 8; nt++) {
                o0[nt][0] *= c0; o0[nt][1] *= c0;
                o0[nt][2] *= c1; o0[nt][3] *= c1;
            }
        }
        {
            float mt0 = -INFINITY, mt1 = -INFINITY;
#pragma unroll
            for (int nt = 0; nt < 8; nt++) {
                mt0 = fmaxf(mt0, fmaxf(s1[nt][0], s1[nt][1]));
                mt1 = fmaxf(mt1, fmaxf(s1[nt][2], s1[nt][3]));
            }
            mt0 = fmaxf(mt0, __shfl_xor_sync(0xffffffffu, mt0, 1));
            mt0 = fmaxf(mt0, __shfl_xor_sync(0xffffffffu, mt0, 2));
            mt1 = fmaxf(mt1, __shfl_xor_sync(0xffffffffu, mt1, 1));
            mt1 = fmaxf(mt1, __shfl_xor_sync(0xffffffffu, mt1, 2));
            float mn0 = fmaxf(m10, mt0), mn1 = fmaxf(m11, mt1);
            float c0 = exp2f(m10 - mn0), c1 = exp2f(m11 - mn1);
            m10 = mn0; m11 = mn1;
            float rs0 = 0.f, rs1 = 0.f;
#pragma unroll
            for (int nt = 0; nt < 8; nt++) {
                float p0 = exp2f(s1[nt][0] - mn0);
                float p1 = exp2f(s1[nt][1] - mn0);
                float p2 = exp2f(s1[nt][2] - mn1);
                float p3 = exp2f(s1[nt][3] - mn1);
                rs0 += p0 + p1; rs1 += p2 + p3;
                uint2 w0 = { f2tf(p0), f2tf(p1) };
                uint2 w1 = { f2tf(p2), f2tf(p3) };
                *(uint2*)&Ps[(r0 + 16) * LTT + nt * 8 + 2 * fc] = w0;
                *(uint2*)&Ps[(r0 + 24) * LTT + nt * 8 + 2 * fc] = w1;
            }
            rs0 += __shfl_xor_sync(0xffffffffu, rs0, 1);
            rs0 += __shfl_xor_sync(0xffffffffu, rs0, 2);
            rs1 += __shfl_xor_sync(0xffffffffu, rs1, 1);
            rs1 += __shfl_xor_sync(0xffffffffu, rs1, 2);
            l10 = l10 * c0 + rs0;
            l11 = l11 * c1 + rs1;
#pragma unroll
            for (int nt = 0; nt < 8; nt++) {
                o1[nt][0] *= c0; o1[nt][1] *= c0;
                o1[nt][2] *= c1; o1[nt][3] *= c1;
            }
        }
        __syncwarp();

#pragma unroll
        for (int ks = 0; ks < 8; ks++) {
            uint32_t af0[4], af1[4], bf[8][2];
            af0[0] = Ps[r0 * LTT + ks * 8 + fc];
            af0[1] = Ps[(r0 + 8) * LTT + ks * 8 + fc];
            af0[2] = Ps[r0 * LTT + ks * 8 + fc + 4];
            af0[3] = Ps[(r0 + 8) * LTT + ks * 8 + fc + 4];
            af1[0] = Ps[(r0 + 16) * LTT + ks * 8 + fc];
            af1[1] = Ps[(r0 + 24) * LTT + ks * 8 + fc];
            af1[2] = Ps[(r0 + 16) * LTT + ks * 8 + fc + 4];
            af1[3] = Ps[(r0 + 24) * LTT + ks * 8 + fc + 4];
#pragma unroll
            for (int nt = 0; nt < 8; nt++) {
                bf[nt][0] = Vs[(ks * 8 + fc) * LTV + nt * 8 + fr];
                bf[nt][1] = Vs[(ks * 8 + fc + 4) * LTV + nt * 8 + fr];
            }
#pragma unroll
            for (int nt = 0; nt < 8; nt++) {
                mma_tf32(o0[nt], af0, bf[nt]);
                mma_tf32(o1[nt], af1, bf[nt]);
            }
        }
    }

    {
        float i00 = 1.f / l00, i01 = 1.f / l01, i10 = 1.f / l10, i11 = 1.f / l11;
        const int qr = q0 + wid * 32 + fr;
        float* b0 = g_attn + (size_t)(n * SEQ + qr) * (NH * HD) + h * HD;
        float* b1 = g_attn + (size_t)(n * SEQ + qr + 8) * (NH * HD) + h * HD;
        float* b2 = g_attn + (size_t)(n * SEQ + qr + 16) * (NH * HD) + h * HD;
        float* b3 = g_attn + (size_t)(n * SEQ + qr + 24) * (NH * HD) + h * HD;
#pragma unroll
        for (int nt = 0; nt < 8; nt++) {
            uint2 w0 = { f2tf(o0[nt][0] * i00), f2tf(o0[nt][1] * i00) };
            uint2 w1 = { f2tf(o0[nt][2] * i01), f2tf(o0[nt][3] * i01) };
            uint2 w2 = { f2tf(o1[nt][0] * i10), f2tf(o1[nt][1] * i10) };
            uint2 w3 = { f2tf(o1[nt][2] * i11), f2tf(o1[nt][3] * i11) };
            *(uint2*)(b0 + nt * 8 + 2 * fc) = w0;
            *(uint2*)(b1 + nt * 8 + 2 * fc) = w1;
            *(uint2*)(b2 + nt * 8 + 2 * fc) = w2;
            *(uint2*)(b3 + nt * 8 + 2 * fc) = w3;
        }
    }
}

// =====================================================================
// launch
// =====================================================================
extern "C" void kernel_launch(void* const* d_in, const int* in_sizes, int n_in,
                              void* d_out, int out_size)
{
    const float* x  = (const float*)d_in[0];
    const float* Wq = (const float*)d_in[1];
    const float* Wk = (const float*)d_in[2];
    const float* Wv = (const float*)d_in[3];
    const float* Wo = (const float*)d_in[4];
    const float* bo = (const float*)d_in[5];
    float* out = (float*)d_out;

    float *qp, *kp, *vp;
    cudaGetSymbolAddress((void**)&qp, g_q);
    cudaGetSymbolAddress((void**)&kp, g_k);
    cudaGetSymbolAddress((void**)&vp, g_v);

    preround<<<TOT4 / 256, 256>>>(x, Wq, Wk, Wv, Wo);

    cudaFuncSetAttribute(gemm_qkv, cudaFuncAttributeMaxDynamicSharedMemorySize, GSMEM_DYN);
    cudaFuncSetAttribute(gemm_out, cudaFuncAttributeMaxDynamicSharedMemorySize, GSMEM_DYN);

    // fused QKV projections: 8 x 32 = 256 CTAs (one wave at 2 CTAs/SM)
    gemm_qkv<<<dim3(8, MROWS / 128), 256, GSMEM_DYN>>>(qp, kp, vp);

    // attention
    int smemf = (64 * LTK + 64 * LTV + 128 * LTT) * (int)sizeof(uint32_t);
    cudaFuncSetAttribute(flash_mma, cudaFuncAttributeMaxDynamicSharedMemorySize, smemf);
    flash_mma<<<dim3(SEQ / 128, NH, NB), 128, smemf>>>();

    // output projection + bias: 4 x 32 = 128 CTAs
    gemm_out<<<dim3(EMB / 256, MROWS / 128), 256, GSMEM_DYN>>>(bo, out);
}